// round 11
// baseline (speedup 1.0000x reference)
#include <cuda_runtime.h>
#include <cuda_bf16.h>
#include <cuda_fp16.h>
#include <math.h>

#define DM 256
#define HEADS 8
#define DH 32
#define LEVELS 4
#define POINTS 4
#define DFFN 1024
#define BATCH 8
#define NQ 300
#define NC 16
#define LQ (NQ*NC)          // 4800
#define TOK (BATCH*LQ)      // 38400
#define LEN_IN 5440
#define VROWS (BATCH*LEN_IN) // 43520

// ---------------- scratch (static device memory; no runtime allocation) ----
__device__ float g_t[TOK*DM];
__device__ float g_q[TOK*DM];        // deform output
__device__ float g_x[TOK*DM];
__device__ float g_y[TOK*DM];
__device__ float g_big[TOK*DFFN];    // fp32 FFN hidden; also aliased as half qkv
__device__ __half g_val[VROWS*DM];   // projected value (fp16)
__device__ float g_attw[TOK*HEADS*LEVELS*POINTS];

// pre-split weights (bf16 hi/lo), concatenated
#define OFF_SA_IN   0           // 768*256
#define OFF_SA_OUT  196608      // 256*256
#define OFF_CA_VAL  262144
#define OFF_CA_OFF  327680
#define OFF_CA_ATTW 393216      // 128*256
#define OFF_CA_OUT  425984
#define OFF_LIN1    491520      // 1024*256
#define OFF_LIN2    753664      // 256*1024
#define W_TOTAL     1015808
__device__ __nv_bfloat16 g_wh[W_TOTAL];
__device__ __nv_bfloat16 g_wl[W_TOTAL];

// ---------------- combined weight split kernel (ONE launch) ----------------
__global__ void split_all_kernel(const float* __restrict__ s0,
                                 const float* __restrict__ s1,
                                 const float* __restrict__ s2,
                                 const float* __restrict__ s3,
                                 const float* __restrict__ s4,
                                 const float* __restrict__ s5,
                                 const float* __restrict__ s6,
                                 const float* __restrict__ s7,
                                 __nv_bfloat16* __restrict__ wh,
                                 __nv_bfloat16* __restrict__ wl)
{
    int i = blockIdx.x * 256 + threadIdx.x;
    if (i >= W_TOTAL) return;
    const float* src; int base;
    if      (i < OFF_SA_OUT)  { src = s0; base = OFF_SA_IN;   }
    else if (i < OFF_CA_VAL)  { src = s1; base = OFF_SA_OUT;  }
    else if (i < OFF_CA_OFF)  { src = s2; base = OFF_CA_VAL;  }
    else if (i < OFF_CA_ATTW) { src = s3; base = OFF_CA_OFF;  }
    else if (i < OFF_CA_OUT)  { src = s4; base = OFF_CA_ATTW; }
    else if (i < OFF_LIN1)    { src = s5; base = OFF_CA_OUT;  }
    else if (i < OFF_LIN2)    { src = s6; base = OFF_LIN1;    }
    else                      { src = s7; base = OFF_LIN2;    }
    float x = src[i - base];
    __nv_bfloat16 h = __float2bfloat16_rn(x);
    wh[i] = h;
    wl[i] = __float2bfloat16_rn(x - __bfloat162float(h));
}

// ---------------- bf16 helpers ---------------------------------------------
__device__ __forceinline__ unsigned pk(float x, float y) {
    __nv_bfloat162 v = __floats2bfloat162_rn(x, y);
    return *reinterpret_cast<unsigned*>(&v);
}

__device__ __forceinline__ void cvt4(float4 v, unsigned& w0h, unsigned& w1h,
                                     unsigned& w0l, unsigned& w1l) {
    float x0 = v.x, x1 = v.y, x2 = v.z, x3 = v.w;
    float h0 = __bfloat162float(__float2bfloat16_rn(x0));
    float h1 = __bfloat162float(__float2bfloat16_rn(x1));
    float h2 = __bfloat162float(__float2bfloat16_rn(x2));
    float h3 = __bfloat162float(__float2bfloat16_rn(x3));
    w0h = pk(h0, h1); w1h = pk(h2, h3);
    w0l = pk(x0 - h0, x1 - h1); w1l = pk(x2 - h2, x3 - h3);
}

__device__ __forceinline__ void mma16(float* c, const unsigned* a, const unsigned* b) {
    asm volatile(
        "mma.sync.aligned.m16n8k16.row.col.f32.bf16.bf16.f32 "
        "{%0,%1,%2,%3}, {%4,%5,%6,%7}, {%8,%9}, {%0,%1,%2,%3};\n"
        : "+f"(c[0]), "+f"(c[1]), "+f"(c[2]), "+f"(c[3])
        : "r"(a[0]), "r"(a[1]), "r"(a[2]), "r"(a[3]), "r"(b[0]), "r"(b[1]));
}

__device__ __forceinline__ void ldsm4(unsigned& r0, unsigned& r1,
                                      unsigned& r2, unsigned& r3, unsigned addr) {
    asm volatile("ldmatrix.sync.aligned.m8n8.x4.shared.b16 {%0,%1,%2,%3}, [%4];"
                 : "=r"(r0), "=r"(r1), "=r"(r2), "=r"(r3) : "r"(addr));
}

// ---------------- 3xBF16 GEMM, 128x128 tile, double-buffered ----------------
// C = (A1[+A2]) @ W^T + bias. W pre-split bf16 hi/lo. One sync per k-tile.
// outh: 0 -> fp32 output, 1 -> fp16 output (C cast to __half*).
// maskp[row]!=0 -> output row zeroed (value GEMM).
#define ROWW 12   // words per padded smem row (48 bytes)
#define BUFB (128*ROWW*4)   // 6144 bytes per buffer
__global__ __launch_bounds__(256, 2)
void gemm_bf3_kernel(const float* __restrict__ A1,
                     const float* __restrict__ A2,
                     const __nv_bfloat16* __restrict__ Wh,
                     const __nv_bfloat16* __restrict__ Wl,
                     const float* __restrict__ bias,
                     const unsigned char* __restrict__ maskp,
                     void* __restrict__ Cv,
                     int M, int N, int K, int ldc, int relu, int outh)
{
    __shared__ unsigned Ah[2][128][ROWW], Al[2][128][ROWW];
    __shared__ unsigned Bh[2][128][ROWW], Bl[2][128][ROWW];

    int tid  = threadIdx.x;                     // 256 threads = 8 warps
    int bm   = blockIdx.y << 7;
    int bn   = blockIdx.x << 7;
    int warp = tid >> 5, lane = tid & 31;
    int wm = warp & 1, wn = warp >> 1;          // 2 (M) x 4 (N) warps
    int g = lane >> 2, t = lane & 3;

    int lrow = tid >> 2;                        // 0..63
    int kc   = (tid & 3) << 2;                  // 0,4,8,12

    const float* Ap0 = A1 + (size_t)(bm + lrow) * K + kc;
    const float* Ap1 = A1 + (size_t)(bm + lrow + 64) * K + kc;
    const float* Aq0 = A2 ? A2 + (size_t)(bm + lrow) * K + kc : (const float*)0;
    const float* Aq1 = A2 ? A2 + (size_t)(bm + lrow + 64) * K + kc : (const float*)0;
    const uint2* Whp0 = (const uint2*)(Wh + (size_t)(bn + lrow) * K + kc);
    const uint2* Whp1 = (const uint2*)(Wh + (size_t)(bn + lrow + 64) * K + kc);
    const uint2* Wlp0 = (const uint2*)(Wl + (size_t)(bn + lrow) * K + kc);
    const uint2* Wlp1 = (const uint2*)(Wl + (size_t)(bn + lrow + 64) * K + kc);

    unsigned saAh = (unsigned)__cvta_generic_to_shared(&Ah[0][0][0]);
    unsigned saAl = (unsigned)__cvta_generic_to_shared(&Al[0][0][0]);
    unsigned saBh = (unsigned)__cvta_generic_to_shared(&Bh[0][0][0]);
    unsigned saBl = (unsigned)__cvta_generic_to_shared(&Bl[0][0][0]);

    unsigned adA_h[4], adA_l[4], adB_h[2], adB_l[2];
    {
        int rA   = lane & 15;
        unsigned offA = (lane >> 4) << 4;
#pragma unroll
        for (int mt = 0; mt < 4; mt++) {
            unsigned ro = (unsigned)(wm*64 + mt*16 + rA) * 48 + offA;
            adA_h[mt] = saAh + ro;
            adA_l[mt] = saAl + ro;
        }
#pragma unroll
        for (int p = 0; p < 2; p++) {
            int ntSel = 2*p + (lane >> 4);
            unsigned ro = (unsigned)(wn*32 + ntSel*8 + (lane & 7)) * 48
                        + (((lane >> 3) & 1) << 4);
            adB_h[p] = saBh + ro;
            adB_l[p] = saBl + ro;
        }
    }

    float c[4][4][4];
#pragma unroll
    for (int mt = 0; mt < 4; mt++)
#pragma unroll
        for (int nt = 0; nt < 4; nt++)
#pragma unroll
            for (int r = 0; r < 4; r++) c[mt][nt][r] = 0.f;

    const int NIT = K >> 4;
    int kw = kc >> 1;

    // prologue: tile 0 -> regs -> buffer 0
    float4 pa0 = *(const float4*)(Ap0);
    float4 pa1 = *(const float4*)(Ap1);
    if (A2) {
        float4 q0 = *(const float4*)(Aq0);
        float4 q1 = *(const float4*)(Aq1);
        pa0.x += q0.x; pa0.y += q0.y; pa0.z += q0.z; pa0.w += q0.w;
        pa1.x += q1.x; pa1.y += q1.y; pa1.z += q1.z; pa1.w += q1.w;
    }
    uint2 wb0h = Whp0[0], wb1h = Whp1[0];
    uint2 wb0l = Wlp0[0], wb1l = Wlp1[0];
    {
        unsigned w0h, w1h, w0l, w1l;
        cvt4(pa0, w0h, w1h, w0l, w1l);
        *(uint2*)&Ah[0][lrow][kw]    = make_uint2(w0h, w1h);
        *(uint2*)&Al[0][lrow][kw]    = make_uint2(w0l, w1l);
        cvt4(pa1, w0h, w1h, w0l, w1l);
        *(uint2*)&Ah[0][lrow+64][kw] = make_uint2(w0h, w1h);
        *(uint2*)&Al[0][lrow+64][kw] = make_uint2(w0l, w1l);
        *(uint2*)&Bh[0][lrow][kw]    = wb0h;
        *(uint2*)&Bh[0][lrow+64][kw] = wb1h;
        *(uint2*)&Bl[0][lrow][kw]    = wb0l;
        *(uint2*)&Bl[0][lrow+64][kw] = wb1l;
    }
    __syncthreads();

    int buf = 0;
    for (int it = 0; it < NIT; ++it) {
        if (it + 1 < NIT) {
            int off = (it + 1) << 4;
            int woff = (it + 1) << 2;
            pa0 = *(const float4*)(Ap0 + off);
            pa1 = *(const float4*)(Ap1 + off);
            if (A2) {
                float4 q0 = *(const float4*)(Aq0 + off);
                float4 q1 = *(const float4*)(Aq1 + off);
                pa0.x += q0.x; pa0.y += q0.y; pa0.z += q0.z; pa0.w += q0.w;
                pa1.x += q1.x; pa1.y += q1.y; pa1.z += q1.z; pa1.w += q1.w;
            }
            wb0h = Whp0[woff]; wb1h = Whp1[woff];
            wb0l = Wlp0[woff]; wb1l = Wlp1[woff];
        }

        unsigned bo = (unsigned)buf * BUFB;
        unsigned bh[4][2], bl[4][2];
        ldsm4(bh[0][0], bh[0][1], bh[1][0], bh[1][1], adB_h[0] + bo);
        ldsm4(bh[2][0], bh[2][1], bh[3][0], bh[3][1], adB_h[1] + bo);
        ldsm4(bl[0][0], bl[0][1], bl[1][0], bl[1][1], adB_l[0] + bo);
        ldsm4(bl[2][0], bl[2][1], bl[3][0], bl[3][1], adB_l[1] + bo);

#pragma unroll
        for (int mt = 0; mt < 4; mt++) {
            unsigned ah[4], al[4];
            ldsm4(ah[0], ah[1], ah[2], ah[3], adA_h[mt] + bo);
            ldsm4(al[0], al[1], al[2], al[3], adA_l[mt] + bo);
#pragma unroll
            for (int nt = 0; nt < 4; nt++) {
                mma16(c[mt][nt], ah, bh[nt]);
                mma16(c[mt][nt], ah, bl[nt]);
                mma16(c[mt][nt], al, bh[nt]);
            }
        }

        if (it + 1 < NIT) {
            int nb = buf ^ 1;
            unsigned w0h, w1h, w0l, w1l;
            cvt4(pa0, w0h, w1h, w0l, w1l);
            *(uint2*)&Ah[nb][lrow][kw]    = make_uint2(w0h, w1h);
            *(uint2*)&Al[nb][lrow][kw]    = make_uint2(w0l, w1l);
            cvt4(pa1, w0h, w1h, w0l, w1l);
            *(uint2*)&Ah[nb][lrow+64][kw] = make_uint2(w0h, w1h);
            *(uint2*)&Al[nb][lrow+64][kw] = make_uint2(w0l, w1l);
            *(uint2*)&Bh[nb][lrow][kw]    = wb0h;
            *(uint2*)&Bh[nb][lrow+64][kw] = wb1h;
            *(uint2*)&Bl[nb][lrow][kw]    = wb0l;
            *(uint2*)&Bl[nb][lrow+64][kw] = wb1l;
            __syncthreads();
        }
        buf ^= 1;
    }

    // epilogue: bias (+relu) (+row mask), fp32 or fp16 output
    float lob = relu ? 0.f : __int_as_float(0xff800000);
    float* Cf = (float*)Cv;
    __half* Ch = (__half*)Cv;
#pragma unroll
    for (int mt = 0; mt < 4; mt++) {
        int row0 = bm + wm*64 + mt*16 + g;
        float mk0 = 1.f, mk1 = 1.f;
        if (maskp) {
            mk0 = maskp[row0]     ? 0.f : 1.f;
            mk1 = maskp[row0 + 8] ? 0.f : 1.f;
        }
#pragma unroll
        for (int nt = 0; nt < 4; nt++) {
            int col = bn + wn*32 + nt*8 + 2*t;
            float2 bi = *(const float2*)(bias + col);
            float o0x = fmaxf(c[mt][nt][0] + bi.x, lob) * mk0;
            float o0y = fmaxf(c[mt][nt][1] + bi.y, lob) * mk0;
            float o1x = fmaxf(c[mt][nt][2] + bi.x, lob) * mk1;
            float o1y = fmaxf(c[mt][nt][3] + bi.y, lob) * mk1;
            if (!outh) {
                *(float2*)&Cf[(size_t)row0 * ldc + col]     = make_float2(o0x, o0y);
                *(float2*)&Cf[(size_t)(row0+8) * ldc + col] = make_float2(o1x, o1y);
            } else {
                __half2 h0 = __floats2half2_rn(o0x, o0y);
                __half2 h1 = __floats2half2_rn(o1x, o1y);
                *(__half2*)&Ch[(size_t)row0 * ldc + col]     = h0;
                *(__half2*)&Ch[(size_t)(row0+8) * ldc + col] = h1;
            }
        }
    }
}

// ---------------- self-attention over 16-token sequences (fp16 qkv) ---------
__global__ void self_attn_kernel(const __half* __restrict__ qkv,
                                 float* __restrict__ out)
{
    __shared__ float sQ[NC][DM];
    __shared__ float sK[NC][DM];
    __shared__ float sV[NC][DM];
    int s = blockIdx.x;
    int tid = threadIdx.x;
    const __half* base = qkv + (size_t)s * NC * 768;
    // 8 halfs per uint4 load; NC*DM/8 = 512 slots per matrix
    for (int idx = tid; idx < NC * DM / 8; idx += 128) {
        int i = idx >> 5, c8 = (idx & 31) << 3;
        const __half* rb = base + i * 768;
#pragma unroll
        for (int m = 0; m < 3; m++) {
            uint4 v = *(const uint4*)(rb + m*256 + c8);
            const __half2* hp = (const __half2*)&v;
            float2 f0 = __half22float2(hp[0]);
            float2 f1 = __half22float2(hp[1]);
            float2 f2 = __half22float2(hp[2]);
            float2 f3 = __half22float2(hp[3]);
            float* dst = (m == 0 ? &sQ[i][c8] : (m == 1 ? &sK[i][c8] : &sV[i][c8]));
            *(float4*)dst       = make_float4(f0.x, f0.y, f1.x, f1.y);
            *(float4*)(dst + 4) = make_float4(f2.x, f2.y, f3.x, f3.y);
        }
    }
    __syncthreads();

    int h = tid >> 4, i = tid & 15;
    const float scale = 0.1767766952966369f;  // 1/sqrt(32)
    float sc[NC];
    float mx = -1e30f;
#pragma unroll
    for (int j = 0; j < NC; j++) {
        float acc = 0.f;
#pragma unroll
        for (int d = 0; d < DH; d++) acc += sQ[i][h*DH + d] * sK[j][h*DH + d];
        acc *= scale;
        sc[j] = acc;
        mx = fmaxf(mx, acc);
    }
    float sum = 0.f;
#pragma unroll
    for (int j = 0; j < NC; j++) { sc[j] = expf(sc[j] - mx); sum += sc[j]; }
    float inv = 1.f / sum;
#pragma unroll
    for (int d = 0; d < DH; d++) {
        float acc = 0.f;
#pragma unroll
        for (int j = 0; j < NC; j++) acc += sc[j] * sV[j][h*DH + d];
        out[((size_t)s * NC + i) * DM + h*DH + d] = acc * inv;
    }
}

// ---------------- add + layernorm ------------------------------------------
__global__ void add_ln_kernel(const float* __restrict__ a,
                              const float* __restrict__ b,
                              const float* __restrict__ w,
                              const float* __restrict__ bb,
                              float* __restrict__ out)
{
    __shared__ float sred[8];
    __shared__ float smean, svar;
    int row = blockIdx.x, tid = threadIdx.x;
    size_t idx = (size_t)row * DM + tid;
    float x = a[idx] + b[idx];
    float v = x;
#pragma unroll
    for (int o = 16; o; o >>= 1) v += __shfl_xor_sync(0xffffffffu, v, o);
    if ((tid & 31) == 0) sred[tid >> 5] = v;
    __syncthreads();
    if (tid == 0) {
        float s = 0.f;
#pragma unroll
        for (int k = 0; k < 8; k++) s += sred[k];
        smean = s * (1.f / DM);
    }
    __syncthreads();
    float d = x - smean;
    v = d * d;
#pragma unroll
    for (int o = 16; o; o >>= 1) v += __shfl_xor_sync(0xffffffffu, v, o);
    if ((tid & 31) == 0) sred[tid >> 5] = v;
    __syncthreads();
    if (tid == 0) {
        float s = 0.f;
#pragma unroll
        for (int k = 0; k < 8; k++) s += sred[k];
        svar = s * (1.f / DM);
    }
    __syncthreads();
    out[idx] = d * rsqrtf(svar + 1e-5f) * w[tid] + bb[tid];
}

// ---------------- deformable sampling (fp16 value) ---------------------------
__global__ void deform_kernel(const float* __restrict__ off,
                              const float* __restrict__ attw,
                              const float* __restrict__ refp,
                              const __half* __restrict__ val,
                              float* __restrict__ out)
{
    __shared__ float saw[HEADS][16];
    int token = blockIdx.x;
    int bidx  = token / LQ;
    int tid = threadIdx.x;
    int h = tid >> 5, lane = tid & 31;
    int j = lane & 15;

    float w = attw[(size_t)token * (HEADS*16) + h*16 + j];
    float mx = w;
#pragma unroll
    for (int o = 8; o; o >>= 1) mx = fmaxf(mx, __shfl_xor_sync(0xffffffffu, mx, o));
    float e = expf(w - mx);
    float s = e;
#pragma unroll
    for (int o = 8; o; o >>= 1) s += __shfl_xor_sync(0xffffffffu, s, o);
    if (lane < 16) saw[h][lane] = e / s;
    __syncwarp();

    const int Hs[4]     = {64, 32, 16, 8};
    const int Ws[4]     = {64, 32, 16, 8};
    const int starts[4] = {0, 4096, 5120, 5376};

    const float* offp = off + (size_t)token * DM + h * 32;
    const float* refb = refp + (size_t)token * (LEVELS*2);
    const __half* vb = val + ((size_t)bidx * LEN_IN) * DM + h * DH + lane;

    float acc = 0.f;
#pragma unroll
    for (int l = 0; l < LEVELS; l++) {
        int H_ = Hs[l], W_ = Ws[l];
        float rx = refb[l*2 + 0], ry = refb[l*2 + 1];
        const __half* vlev = vb + (size_t)starts[l] * DM;
#pragma unroll
        for (int p = 0; p < POINTS; p++) {
            float ox = offp[(l*4 + p)*2 + 0];
            float oy = offp[(l*4 + p)*2 + 1];
            float gx = (rx + ox / W_) * W_ - 0.5f;
            float gy = (ry + oy / H_) * H_ - 0.5f;
            float fx = floorf(gx), fy = floorf(gy);
            int x0 = (int)fx, y0 = (int)fy;
            float ax = gx - fx, ay = gy - fy;
            float aw = saw[h][l*4 + p];
            bool xin0 = (x0 >= 0) && (x0 < W_);
            bool xin1 = (x0 + 1 >= 0) && (x0 + 1 < W_);
            bool yin0 = (y0 >= 0) && (y0 < H_);
            bool yin1 = (y0 + 1 >= 0) && (y0 + 1 < H_);
            float v00 = (xin0 && yin0) ? __half2float(vlev[(size_t)(y0*W_ + x0) * DM]) : 0.f;
            float v01 = (xin1 && yin0) ? __half2float(vlev[(size_t)(y0*W_ + x0 + 1) * DM]) : 0.f;
            float v10 = (xin0 && yin1) ? __half2float(vlev[(size_t)((y0+1)*W_ + x0) * DM]) : 0.f;
            float v11 = (xin1 && yin1) ? __half2float(vlev[(size_t)((y0+1)*W_ + x0 + 1) * DM]) : 0.f;
            float sample = v00*(1.f-ax)*(1.f-ay) + v01*ax*(1.f-ay)
                         + v10*(1.f-ax)*ay       + v11*ax*ay;
            acc += aw * sample;
        }
    }
    out[(size_t)token * DM + h * DH + lane] = acc;
}

// ---------------------------------------------------------------------------
extern "C" void kernel_launch(void* const* d_in, const int* in_sizes, int n_in,
                              void* d_out, int out_size)
{
    const float* tgt   = (const float*)d_in[0];
    const float* qpos  = (const float*)d_in[1];
    const float* refp  = (const float*)d_in[2];
    const float* src   = (const float*)d_in[3];
    const unsigned char* mask = (const unsigned char*)d_in[6];
    const float* sa_in_w  = (const float*)d_in[7];
    const float* sa_in_b  = (const float*)d_in[8];
    const float* sa_out_w = (const float*)d_in[9];
    const float* sa_out_b = (const float*)d_in[10];
    const float* norm2_w  = (const float*)d_in[11];
    const float* norm2_b  = (const float*)d_in[12];
    const float* ca_value_w = (const float*)d_in[13];
    const float* ca_value_b = (const float*)d_in[14];
    const float* ca_off_w   = (const float*)d_in[15];
    const float* ca_off_b   = (const float*)d_in[16];
    const float* ca_attw_w  = (const float*)d_in[17];
    const float* ca_attw_b  = (const float*)d_in[18];
    const float* ca_out_w   = (const float*)d_in[19];
    const float* ca_out_b   = (const float*)d_in[20];
    const float* norm1_w    = (const float*)d_in[21];
    const float* norm1_b    = (const float*)d_in[22];
    const float* lin1_w     = (const float*)d_in[23];
    const float* lin1_b     = (const float*)d_in[24];
    const float* lin2_w     = (const float*)d_in[25];
    const float* lin2_b     = (const float*)d_in[26];
    const float* norm3_w    = (const float*)d_in[27];
    const float* norm3_b    = (const float*)d_in[28];
    float* out = (float*)d_out;

    float *gt, *gq, *gx, *gy, *gbig, *gattw;
    __half *gval;
    __nv_bfloat16 *gwh, *gwl;
    cudaGetSymbolAddress((void**)&gt,   g_t);
    cudaGetSymbolAddress((void**)&gq,   g_q);
    cudaGetSymbolAddress((void**)&gx,   g_x);
    cudaGetSymbolAddress((void**)&gy,   g_y);
    cudaGetSymbolAddress((void**)&gbig, g_big);
    cudaGetSymbolAddress((void**)&gval, g_val);
    cudaGetSymbolAddress((void**)&gattw, g_attw);
    cudaGetSymbolAddress((void**)&gwh,  g_wh);
    cudaGetSymbolAddress((void**)&gwl,  g_wl);

    __half* gqkv = (__half*)gbig;   // alias: fp16 qkv buffer [TOK, 768]
    const unsigned char* nomask = (const unsigned char*)0;

    // ---- weight pre-split: ONE launch --------------------------------------
    split_all_kernel<<<(W_TOTAL + 255) / 256, 256>>>(
        sa_in_w, sa_out_w, ca_value_w, ca_off_w, ca_attw_w, ca_out_w,
        lin1_w, lin2_w, gwh, gwl);

    // ---- stage 1: self-attention -------------------------------------------
    {
        dim3 grid(512 / 128, TOK / 128);
        gemm_bf3_kernel<<<grid, 256>>>(tgt, qpos, gwh+OFF_SA_IN, gwl+OFF_SA_IN,
                                       sa_in_b, nomask, gqkv, TOK, 512, DM, 768, 0, 1);
    }
    {
        dim3 grid(256 / 128, TOK / 128);
        gemm_bf3_kernel<<<grid, 256>>>(tgt, (const float*)0,
                                       gwh+OFF_SA_IN+(size_t)512*DM, gwl+OFF_SA_IN+(size_t)512*DM,
                                       sa_in_b + 512, nomask, gqkv + 512, TOK, 256, DM, 768, 0, 1);
    }
    self_attn_kernel<<<BATCH * NQ, 128>>>(gqkv, gx);
    {
        dim3 grid(256 / 128, TOK / 128);
        gemm_bf3_kernel<<<grid, 256>>>(gx, (const float*)0, gwh+OFF_SA_OUT, gwl+OFF_SA_OUT,
                                       sa_out_b, nomask, gy, TOK, 256, DM, 256, 0, 0);
    }
    add_ln_kernel<<<TOK, 256>>>(tgt, gy, norm2_w, norm2_b, gt);

    // ---- stage 2: deformable cross-attention -------------------------------
    {
        dim3 grid(256 / 128, VROWS / 128);
        gemm_bf3_kernel<<<grid, 256>>>(src, (const float*)0, gwh+OFF_CA_VAL, gwl+OFF_CA_VAL,
                                       ca_value_b, mask, gval, VROWS, 256, DM, 256, 0, 1);
    }
    {
        dim3 grid(256 / 128, TOK / 128);
        gemm_bf3_kernel<<<grid, 256>>>(gt, qpos, gwh+OFF_CA_OFF, gwl+OFF_CA_OFF,
                                       ca_off_b, nomask, gx, TOK, 256, DM, 256, 0, 0);
    }
    {
        dim3 grid(128 / 128, TOK / 128);
        gemm_bf3_kernel<<<grid, 256>>>(gt, qpos, gwh+OFF_CA_ATTW, gwl+OFF_CA_ATTW,
                                       ca_attw_b, nomask, gattw, TOK, 128, DM, 128, 0, 0);
    }
    deform_kernel<<<TOK, 256>>>(gx, gattw, refp, gval, gq);
    {
        dim3 grid(256 / 128, TOK / 128);
        gemm_bf3_kernel<<<grid, 256>>>(gq, (const float*)0, gwh+OFF_CA_OUT, gwl+OFF_CA_OUT,
                                       ca_out_b, nomask, gx, TOK, 256, DM, 256, 0, 0);
    }
    add_ln_kernel<<<TOK, 256>>>(gt, gx, norm1_w, norm1_b, gt);

    // ---- stage 3: FFN ------------------------------------------------------
    {
        dim3 grid(DFFN / 128, TOK / 128);
        gemm_bf3_kernel<<<grid, 256>>>(gt, (const float*)0, gwh+OFF_LIN1, gwl+OFF_LIN1,
                                       lin1_b, nomask, gbig, TOK, DFFN, DM, DFFN, 1, 0);
    }
    {
        dim3 grid(256 / 128, TOK / 128);
        gemm_bf3_kernel<<<grid, 256>>>(gbig, (const float*)0, gwh+OFF_LIN2, gwl+OFF_LIN2,
                                       lin2_b, nomask, gx, TOK, 256, DFFN, 256, 0, 0);
    }
    add_ln_kernel<<<TOK, 256>>>(gt, gx, norm3_w, norm3_b, out);
}

// round 13
// speedup vs baseline: 1.0270x; 1.0270x over previous
#include <cuda_runtime.h>
#include <cuda_bf16.h>
#include <math.h>

#define DM 256
#define HEADS 8
#define DH 32
#define LEVELS 4
#define POINTS 4
#define DFFN 1024
#define BATCH 8
#define NQ 300
#define NC 16
#define LQ (NQ*NC)          // 4800
#define TOK (BATCH*LQ)      // 38400
#define LEN_IN 5440
#define VROWS (BATCH*LEN_IN) // 43520

// ---------------- scratch (static device memory; no runtime allocation) ----
__device__ float g_t[TOK*DM];
__device__ float g_q[TOK*DM];        // deform output
__device__ float g_x[TOK*DM];
__device__ float g_y[TOK*DM];
__device__ float g_big[TOK*DFFN];    // qkv (768) / off+attw (384, ldc) / FFN hidden
__device__ float g_val[VROWS*DM];
__device__ float g_boa[384];         // merged off+attw bias

// pre-split weights (bf16 hi/lo), concatenated
#define OFF_SA_IN   0           // 768*256
#define OFF_SA_OUT  196608      // 256*256
#define OFF_CA_VAL  262144
#define OFF_CA_OFF  327680      // 256*256 ... followed contiguously by attw 128*256
#define OFF_CA_ATTW 393216
#define OFF_CA_OUT  425984
#define OFF_LIN1    491520      // 1024*256
#define OFF_LIN2    753664      // 256*1024
#define W_TOTAL     1015808
__device__ __nv_bfloat16 g_wh[W_TOTAL];
__device__ __nv_bfloat16 g_wl[W_TOTAL];

// ---------------- combined weight split kernel (ONE launch) ----------------
__global__ void split_all_kernel(const float* __restrict__ s0,
                                 const float* __restrict__ s1,
                                 const float* __restrict__ s2,
                                 const float* __restrict__ s3,
                                 const float* __restrict__ s4,
                                 const float* __restrict__ s5,
                                 const float* __restrict__ s6,
                                 const float* __restrict__ s7,
                                 const float* __restrict__ offb,
                                 const float* __restrict__ attwb,
                                 __nv_bfloat16* __restrict__ wh,
                                 __nv_bfloat16* __restrict__ wl,
                                 float* __restrict__ boa)
{
    int i = blockIdx.x * 256 + threadIdx.x;
    if (i < 384) boa[i] = (i < 256) ? offb[i] : attwb[i - 256];
    if (i >= W_TOTAL) return;
    const float* src; int base;
    if      (i < OFF_SA_OUT)  { src = s0; base = OFF_SA_IN;   }
    else if (i < OFF_CA_VAL)  { src = s1; base = OFF_SA_OUT;  }
    else if (i < OFF_CA_OFF)  { src = s2; base = OFF_CA_VAL;  }
    else if (i < OFF_CA_ATTW) { src = s3; base = OFF_CA_OFF;  }
    else if (i < OFF_CA_OUT)  { src = s4; base = OFF_CA_ATTW; }
    else if (i < OFF_LIN1)    { src = s5; base = OFF_CA_OUT;  }
    else if (i < OFF_LIN2)    { src = s6; base = OFF_LIN1;    }
    else                      { src = s7; base = OFF_LIN2;    }
    float x = src[i - base];
    __nv_bfloat16 h = __float2bfloat16_rn(x);
    wh[i] = h;
    wl[i] = __float2bfloat16_rn(x - __bfloat162float(h));
}

// ---------------- bf16 helpers ---------------------------------------------
__device__ __forceinline__ unsigned pk(float x, float y) {
    __nv_bfloat162 v = __floats2bfloat162_rn(x, y);
    return *reinterpret_cast<unsigned*>(&v);
}

__device__ __forceinline__ void cvt4(float4 v, unsigned& w0h, unsigned& w1h,
                                     unsigned& w0l, unsigned& w1l) {
    float x0 = v.x, x1 = v.y, x2 = v.z, x3 = v.w;
    float h0 = __bfloat162float(__float2bfloat16_rn(x0));
    float h1 = __bfloat162float(__float2bfloat16_rn(x1));
    float h2 = __bfloat162float(__float2bfloat16_rn(x2));
    float h3 = __bfloat162float(__float2bfloat16_rn(x3));
    w0h = pk(h0, h1); w1h = pk(h2, h3);
    w0l = pk(x0 - h0, x1 - h1); w1l = pk(x2 - h2, x3 - h3);
}

__device__ __forceinline__ void mma16(float* c, const unsigned* a, const unsigned* b) {
    asm volatile(
        "mma.sync.aligned.m16n8k16.row.col.f32.bf16.bf16.f32 "
        "{%0,%1,%2,%3}, {%4,%5,%6,%7}, {%8,%9}, {%0,%1,%2,%3};\n"
        : "+f"(c[0]), "+f"(c[1]), "+f"(c[2]), "+f"(c[3])
        : "r"(a[0]), "r"(a[1]), "r"(a[2]), "r"(a[3]), "r"(b[0]), "r"(b[1]));
}

__device__ __forceinline__ void ldsm4(unsigned& r0, unsigned& r1,
                                      unsigned& r2, unsigned& r3, unsigned addr) {
    asm volatile("ldmatrix.sync.aligned.m8n8.x4.shared.b16 {%0,%1,%2,%3}, [%4];"
                 : "=r"(r0), "=r"(r1), "=r"(r2), "=r"(r3) : "r"(addr));
}

// ---------------- 3xBF16 GEMM, 128x128 tile, double-buffered ----------------
// C = (A1[+A2]) @ W^T + bias. W pre-split bf16 hi/lo. One sync per k-tile.
// maskp[row]!=0 -> output row zeroed (value GEMM).
#define ROWW 12   // words per padded smem row (48 bytes)
#define BUFB (128*ROWW*4)   // 6144 bytes per buffer
__global__ __launch_bounds__(256, 2)
void gemm_bf3_kernel(const float* __restrict__ A1,
                     const float* __restrict__ A2,
                     const __nv_bfloat16* __restrict__ Wh,
                     const __nv_bfloat16* __restrict__ Wl,
                     const float* __restrict__ bias,
                     const unsigned char* __restrict__ maskp,
                     float* __restrict__ C,
                     int M, int N, int K, int ldc, int relu)
{
    __shared__ unsigned Ah[2][128][ROWW], Al[2][128][ROWW];
    __shared__ unsigned Bh[2][128][ROWW], Bl[2][128][ROWW];

    int tid  = threadIdx.x;                     // 256 threads = 8 warps
    int bm   = blockIdx.y << 7;
    int bn   = blockIdx.x << 7;
    int warp = tid >> 5, lane = tid & 31;
    int wm = warp & 1, wn = warp >> 1;          // 2 (M) x 4 (N) warps
    int g = lane >> 2, t = lane & 3;

    int lrow = tid >> 2;                        // 0..63
    int kc   = (tid & 3) << 2;                  // 0,4,8,12

    const float* Ap0 = A1 + (size_t)(bm + lrow) * K + kc;
    const float* Ap1 = A1 + (size_t)(bm + lrow + 64) * K + kc;
    const float* Aq0 = A2 ? A2 + (size_t)(bm + lrow) * K + kc : (const float*)0;
    const float* Aq1 = A2 ? A2 + (size_t)(bm + lrow + 64) * K + kc : (const float*)0;
    const uint2* Whp0 = (const uint2*)(Wh + (size_t)(bn + lrow) * K + kc);
    const uint2* Whp1 = (const uint2*)(Wh + (size_t)(bn + lrow + 64) * K + kc);
    const uint2* Wlp0 = (const uint2*)(Wl + (size_t)(bn + lrow) * K + kc);
    const uint2* Wlp1 = (const uint2*)(Wl + (size_t)(bn + lrow + 64) * K + kc);

    unsigned saAh = (unsigned)__cvta_generic_to_shared(&Ah[0][0][0]);
    unsigned saAl = (unsigned)__cvta_generic_to_shared(&Al[0][0][0]);
    unsigned saBh = (unsigned)__cvta_generic_to_shared(&Bh[0][0][0]);
    unsigned saBl = (unsigned)__cvta_generic_to_shared(&Bl[0][0][0]);

    unsigned adA_h[4], adA_l[4], adB_h[2], adB_l[2];
    {
        int rA   = lane & 15;
        unsigned offA = (lane >> 4) << 4;
#pragma unroll
        for (int mt = 0; mt < 4; mt++) {
            unsigned ro = (unsigned)(wm*64 + mt*16 + rA) * 48 + offA;
            adA_h[mt] = saAh + ro;
            adA_l[mt] = saAl + ro;
        }
#pragma unroll
        for (int p = 0; p < 2; p++) {
            int ntSel = 2*p + (lane >> 4);
            unsigned ro = (unsigned)(wn*32 + ntSel*8 + (lane & 7)) * 48
                        + (((lane >> 3) & 1) << 4);
            adB_h[p] = saBh + ro;
            adB_l[p] = saBl + ro;
        }
    }

    float c[4][4][4];
#pragma unroll
    for (int mt = 0; mt < 4; mt++)
#pragma unroll
        for (int nt = 0; nt < 4; nt++)
#pragma unroll
            for (int r = 0; r < 4; r++) c[mt][nt][r] = 0.f;

    const int NIT = K >> 4;
    int kw = kc >> 1;

    float4 pa0 = *(const float4*)(Ap0);
    float4 pa1 = *(const float4*)(Ap1);
    if (A2) {
        float4 q0 = *(const float4*)(Aq0);
        float4 q1 = *(const float4*)(Aq1);
        pa0.x += q0.x; pa0.y += q0.y; pa0.z += q0.z; pa0.w += q0.w;
        pa1.x += q1.x; pa1.y += q1.y; pa1.z += q1.z; pa1.w += q1.w;
    }
    uint2 wb0h = Whp0[0], wb1h = Whp1[0];
    uint2 wb0l = Wlp0[0], wb1l = Wlp1[0];
    {
        unsigned w0h, w1h, w0l, w1l;
        cvt4(pa0, w0h, w1h, w0l, w1l);
        *(uint2*)&Ah[0][lrow][kw]    = make_uint2(w0h, w1h);
        *(uint2*)&Al[0][lrow][kw]    = make_uint2(w0l, w1l);
        cvt4(pa1, w0h, w1h, w0l, w1l);
        *(uint2*)&Ah[0][lrow+64][kw] = make_uint2(w0h, w1h);
        *(uint2*)&Al[0][lrow+64][kw] = make_uint2(w0l, w1l);
        *(uint2*)&Bh[0][lrow][kw]    = wb0h;
        *(uint2*)&Bh[0][lrow+64][kw] = wb1h;
        *(uint2*)&Bl[0][lrow][kw]    = wb0l;
        *(uint2*)&Bl[0][lrow+64][kw] = wb1l;
    }
    __syncthreads();

    int buf = 0;
    for (int it = 0; it < NIT; ++it) {
        if (it + 1 < NIT) {
            int off = (it + 1) << 4;
            int woff = (it + 1) << 2;
            pa0 = *(const float4*)(Ap0 + off);
            pa1 = *(const float4*)(Ap1 + off);
            if (A2) {
                float4 q0 = *(const float4*)(Aq0 + off);
                float4 q1 = *(const float4*)(Aq1 + off);
                pa0.x += q0.x; pa0.y += q0.y; pa0.z += q0.z; pa0.w += q0.w;
                pa1.x += q1.x; pa1.y += q1.y; pa1.z += q1.z; pa1.w += q1.w;
            }
            wb0h = Whp0[woff]; wb1h = Whp1[woff];
            wb0l = Wlp0[woff]; wb1l = Wlp1[woff];
        }

        unsigned bo = (unsigned)buf * BUFB;
        unsigned bh[4][2], bl[4][2];
        ldsm4(bh[0][0], bh[0][1], bh[1][0], bh[1][1], adB_h[0] + bo);
        ldsm4(bh[2][0], bh[2][1], bh[3][0], bh[3][1], adB_h[1] + bo);
        ldsm4(bl[0][0], bl[0][1], bl[1][0], bl[1][1], adB_l[0] + bo);
        ldsm4(bl[2][0], bl[2][1], bl[3][0], bl[3][1], adB_l[1] + bo);

#pragma unroll
        for (int mt = 0; mt < 4; mt++) {
            unsigned ah[4], al[4];
            ldsm4(ah[0], ah[1], ah[2], ah[3], adA_h[mt] + bo);
            ldsm4(al[0], al[1], al[2], al[3], adA_l[mt] + bo);
#pragma unroll
            for (int nt = 0; nt < 4; nt++) {
                mma16(c[mt][nt], ah, bh[nt]);
                mma16(c[mt][nt], ah, bl[nt]);
                mma16(c[mt][nt], al, bh[nt]);
            }
        }

        if (it + 1 < NIT) {
            int nb = buf ^ 1;
            unsigned w0h, w1h, w0l, w1l;
            cvt4(pa0, w0h, w1h, w0l, w1l);
            *(uint2*)&Ah[nb][lrow][kw]    = make_uint2(w0h, w1h);
            *(uint2*)&Al[nb][lrow][kw]    = make_uint2(w0l, w1l);
            cvt4(pa1, w0h, w1h, w0l, w1l);
            *(uint2*)&Ah[nb][lrow+64][kw] = make_uint2(w0h, w1h);
            *(uint2*)&Al[nb][lrow+64][kw] = make_uint2(w0l, w1l);
            *(uint2*)&Bh[nb][lrow][kw]    = wb0h;
            *(uint2*)&Bh[nb][lrow+64][kw] = wb1h;
            *(uint2*)&Bl[nb][lrow][kw]    = wb0l;
            *(uint2*)&Bl[nb][lrow+64][kw] = wb1l;
            __syncthreads();
        }
        buf ^= 1;
    }

    // epilogue: bias (+relu) (+row mask)
    float lob = relu ? 0.f : __int_as_float(0xff800000);
#pragma unroll
    for (int mt = 0; mt < 4; mt++) {
        int row0 = bm + wm*64 + mt*16 + g;
        float mk0 = 1.f, mk1 = 1.f;
        if (maskp) {
            mk0 = maskp[row0]     ? 0.f : 1.f;
            mk1 = maskp[row0 + 8] ? 0.f : 1.f;
        }
#pragma unroll
        for (int nt = 0; nt < 4; nt++) {
            int col = bn + wn*32 + nt*8 + 2*t;
            float2 bi = *(const float2*)(bias + col);
            float2 o0, o1;
            o0.x = fmaxf(c[mt][nt][0] + bi.x, lob) * mk0;
            o0.y = fmaxf(c[mt][nt][1] + bi.y, lob) * mk0;
            o1.x = fmaxf(c[mt][nt][2] + bi.x, lob) * mk1;
            o1.y = fmaxf(c[mt][nt][3] + bi.y, lob) * mk1;
            *(float2*)&C[(size_t)row0 * ldc + col]       = o0;
            *(float2*)&C[(size_t)(row0+8) * ldc + col]   = o1;
        }
    }
}

// ---------------- self-attention over 16-token sequences --------------------
__global__ void self_attn_kernel(const float* __restrict__ qkv,
                                 float* __restrict__ out)
{
    __shared__ float sQ[NC][DM];
    __shared__ float sK[NC][DM];
    __shared__ float sV[NC][DM];
    int s = blockIdx.x;
    int tid = threadIdx.x;
    const float* base = qkv + (size_t)s * NC * 768;
    for (int idx = tid; idx < NC * DM / 4; idx += 128) {
        int i = idx >> 6, c4 = (idx & 63) << 2;
        const float* rb = base + i * 768;
        *(float4*)&sQ[i][c4] = *(const float4*)(rb + c4);
        *(float4*)&sK[i][c4] = *(const float4*)(rb + 256 + c4);
        *(float4*)&sV[i][c4] = *(const float4*)(rb + 512 + c4);
    }
    __syncthreads();

    int h = tid >> 4, i = tid & 15;
    const float scale = 0.1767766952966369f;  // 1/sqrt(32)
    float sc[NC];
    float mx = -1e30f;
#pragma unroll
    for (int j = 0; j < NC; j++) {
        float acc = 0.f;
#pragma unroll
        for (int d = 0; d < DH; d++) acc += sQ[i][h*DH + d] * sK[j][h*DH + d];
        acc *= scale;
        sc[j] = acc;
        mx = fmaxf(mx, acc);
    }
    float sum = 0.f;
#pragma unroll
    for (int j = 0; j < NC; j++) { sc[j] = expf(sc[j] - mx); sum += sc[j]; }
    float inv = 1.f / sum;
#pragma unroll
    for (int d = 0; d < DH; d++) {
        float acc = 0.f;
#pragma unroll
        for (int j = 0; j < NC; j++) acc += sc[j] * sV[j][h*DH + d];
        out[((size_t)s * NC + i) * DM + h*DH + d] = acc * inv;
    }
}

// ---------------- add + layernorm ------------------------------------------
__global__ void add_ln_kernel(const float* __restrict__ a,
                              const float* __restrict__ b,
                              const float* __restrict__ w,
                              const float* __restrict__ bb,
                              float* __restrict__ out)
{
    __shared__ float sred[8];
    __shared__ float smean, svar;
    int row = blockIdx.x, tid = threadIdx.x;
    size_t idx = (size_t)row * DM + tid;
    float x = a[idx] + b[idx];
    float v = x;
#pragma unroll
    for (int o = 16; o; o >>= 1) v += __shfl_xor_sync(0xffffffffu, v, o);
    if ((tid & 31) == 0) sred[tid >> 5] = v;
    __syncthreads();
    if (tid == 0) {
        float s = 0.f;
#pragma unroll
        for (int k = 0; k < 8; k++) s += sred[k];
        smean = s * (1.f / DM);
    }
    __syncthreads();
    float d = x - smean;
    v = d * d;
#pragma unroll
    for (int o = 16; o; o >>= 1) v += __shfl_xor_sync(0xffffffffu, v, o);
    if ((tid & 31) == 0) sred[tid >> 5] = v;
    __syncthreads();
    if (tid == 0) {
        float s = 0.f;
#pragma unroll
        for (int k = 0; k < 8; k++) s += sred[k];
        svar = s * (1.f / DM);
    }
    __syncthreads();
    out[idx] = d * rsqrtf(svar + 1e-5f) * w[tid] + bb[tid];
}

// ---------------- deformable sampling ---------------------------------------
// offattw: [token][384] = 256 offsets + 128 attw logits, ldc 384.
__global__ void deform_kernel(const float* __restrict__ offattw,
                              const float* __restrict__ refp,
                              const float* __restrict__ val,
                              float* __restrict__ out)
{
    __shared__ float saw[HEADS][16];
    int token = blockIdx.x;
    int bidx  = token / LQ;
    int tid = threadIdx.x;
    int h = tid >> 5, lane = tid & 31;
    int j = lane & 15;

    const float* rowp = offattw + (size_t)token * 384;

    float w = rowp[256 + h*16 + j];
    float mx = w;
#pragma unroll
    for (int o = 8; o; o >>= 1) mx = fmaxf(mx, __shfl_xor_sync(0xffffffffu, mx, o));
    float e = expf(w - mx);
    float s = e;
#pragma unroll
    for (int o = 8; o; o >>= 1) s += __shfl_xor_sync(0xffffffffu, s, o);
    if (lane < 16) saw[h][lane] = e / s;
    __syncwarp();

    const int Hs[4]     = {64, 32, 16, 8};
    const int Ws[4]     = {64, 32, 16, 8};
    const int starts[4] = {0, 4096, 5120, 5376};

    const float* offp = rowp + h * 32;
    const float* refb = refp + (size_t)token * (LEVELS*2);
    const float* vb = val + ((size_t)bidx * LEN_IN) * DM + h * DH + lane;

    float acc = 0.f;
#pragma unroll
    for (int l = 0; l < LEVELS; l++) {
        int H_ = Hs[l], W_ = Ws[l];
        float rx = refb[l*2 + 0], ry = refb[l*2 + 1];
        const float* vlev = vb + (size_t)starts[l] * DM;
#pragma unroll
        for (int p = 0; p < POINTS; p++) {
            float ox = offp[(l*4 + p)*2 + 0];
            float oy = offp[(l*4 + p)*2 + 1];
            float gx = (rx + ox / W_) * W_ - 0.5f;
            float gy = (ry + oy / H_) * H_ - 0.5f;
            float fx = floorf(gx), fy = floorf(gy);
            int x0 = (int)fx, y0 = (int)fy;
            float ax = gx - fx, ay = gy - fy;
            float aw = saw[h][l*4 + p];
            bool xin0 = (x0 >= 0) && (x0 < W_);
            bool xin1 = (x0 + 1 >= 0) && (x0 + 1 < W_);
            bool yin0 = (y0 >= 0) && (y0 < H_);
            bool yin1 = (y0 + 1 >= 0) && (y0 + 1 < H_);
            float v00 = (xin0 && yin0) ? vlev[(size_t)(y0*W_ + x0) * DM] : 0.f;
            float v01 = (xin1 && yin0) ? vlev[(size_t)(y0*W_ + x0 + 1) * DM] : 0.f;
            float v10 = (xin0 && yin1) ? vlev[(size_t)((y0+1)*W_ + x0) * DM] : 0.f;
            float v11 = (xin1 && yin1) ? vlev[(size_t)((y0+1)*W_ + x0 + 1) * DM] : 0.f;
            float sample = v00*(1.f-ax)*(1.f-ay) + v01*ax*(1.f-ay)
                         + v10*(1.f-ax)*ay       + v11*ax*ay;
            acc += aw * sample;
        }
    }
    out[(size_t)token * DM + h * DH + lane] = acc;
}

// ---------------------------------------------------------------------------
extern "C" void kernel_launch(void* const* d_in, const int* in_sizes, int n_in,
                              void* d_out, int out_size)
{
    const float* tgt   = (const float*)d_in[0];
    const float* qpos  = (const float*)d_in[1];
    const float* refp  = (const float*)d_in[2];
    const float* src   = (const float*)d_in[3];
    const unsigned char* mask = (const unsigned char*)d_in[6];
    const float* sa_in_w  = (const float*)d_in[7];
    const float* sa_in_b  = (const float*)d_in[8];
    const float* sa_out_w = (const float*)d_in[9];
    const float* sa_out_b = (const float*)d_in[10];
    const float* norm2_w  = (const float*)d_in[11];
    const float* norm2_b  = (const float*)d_in[12];
    const float* ca_value_w = (const float*)d_in[13];
    const float* ca_value_b = (const float*)d_in[14];
    const float* ca_off_w   = (const float*)d_in[15];
    const float* ca_off_b   = (const float*)d_in[16];
    const float* ca_attw_w  = (const float*)d_in[17];
    const float* ca_attw_b  = (const float*)d_in[18];
    const float* ca_out_w   = (const float*)d_in[19];
    const float* ca_out_b   = (const float*)d_in[20];
    const float* norm1_w    = (const float*)d_in[21];
    const float* norm1_b    = (const float*)d_in[22];
    const float* lin1_w     = (const float*)d_in[23];
    const float* lin1_b     = (const float*)d_in[24];
    const float* lin2_w     = (const float*)d_in[25];
    const float* lin2_b     = (const float*)d_in[26];
    const float* norm3_w    = (const float*)d_in[27];
    const float* norm3_b    = (const float*)d_in[28];
    float* out = (float*)d_out;

    float *gt, *gq, *gx, *gy, *gbig, *gval, *gboa;
    __nv_bfloat16 *gwh, *gwl;
    cudaGetSymbolAddress((void**)&gt,   g_t);
    cudaGetSymbolAddress((void**)&gq,   g_q);
    cudaGetSymbolAddress((void**)&gx,   g_x);
    cudaGetSymbolAddress((void**)&gy,   g_y);
    cudaGetSymbolAddress((void**)&gbig, g_big);
    cudaGetSymbolAddress((void**)&gval, g_val);
    cudaGetSymbolAddress((void**)&gboa, g_boa);
    cudaGetSymbolAddress((void**)&gwh,  g_wh);
    cudaGetSymbolAddress((void**)&gwl,  g_wl);

    const unsigned char* nomask = (const unsigned char*)0;

    // side stream + events: created once on the (uncaptured) correctness call
    static cudaStream_t s_side = 0;
    static cudaEvent_t  ev_fork = 0, ev_join = 0;
    if (!s_side) {
        cudaStreamCreateWithFlags(&s_side, cudaStreamNonBlocking);
        cudaEventCreateWithFlags(&ev_fork, cudaEventDisableTiming);
        cudaEventCreateWithFlags(&ev_join, cudaEventDisableTiming);
    }

    // ---- weight pre-split: ONE launch --------------------------------------
    split_all_kernel<<<(W_TOTAL + 255) / 256, 256>>>(
        sa_in_w, sa_out_w, ca_value_w, ca_off_w, ca_attw_w, ca_out_w,
        lin1_w, lin2_w, ca_off_b, ca_attw_b, gwh, gwl, gboa);

    // ---- fork: value projection GEMM runs concurrently with stage 1 --------
    cudaEventRecord(ev_fork, 0);
    cudaStreamWaitEvent(s_side, ev_fork, 0);
    {
        dim3 grid(256 / 128, VROWS / 128);
        gemm_bf3_kernel<<<grid, 256, 0, s_side>>>(src, (const float*)0,
                                       gwh+OFF_CA_VAL, gwl+OFF_CA_VAL,
                                       ca_value_b, mask, gval, VROWS, 256, DM, 256, 0);
    }
    cudaEventRecord(ev_join, s_side);

    // ---- stage 1: self-attention -------------------------------------------
    {
        dim3 grid(512 / 128, TOK / 128);
        gemm_bf3_kernel<<<grid, 256>>>(tgt, qpos, gwh+OFF_SA_IN, gwl+OFF_SA_IN,
                                       sa_in_b, nomask, gbig, TOK, 512, DM, 768, 0);
    }
    {
        dim3 grid(256 / 128, TOK / 128);
        gemm_bf3_kernel<<<grid, 256>>>(tgt, (const float*)0,
                                       gwh+OFF_SA_IN+(size_t)512*DM, gwl+OFF_SA_IN+(size_t)512*DM,
                                       sa_in_b + 512, nomask, gbig + 512, TOK, 256, DM, 768, 0);
    }
    self_attn_kernel<<<BATCH * NQ, 128>>>(gbig, gx);
    {
        dim3 grid(256 / 128, TOK / 128);
        gemm_bf3_kernel<<<grid, 256>>>(gx, (const float*)0, gwh+OFF_SA_OUT, gwl+OFF_SA_OUT,
                                       sa_out_b, nomask, gy, TOK, 256, DM, 256, 0);
    }
    add_ln_kernel<<<TOK, 256>>>(tgt, gy, norm2_w, norm2_b, gt);

    // ---- stage 2: merged off+attw GEMM (N=384, ldc=384, out in g_big) -------
    {
        dim3 grid(384 / 128, TOK / 128);
        gemm_bf3_kernel<<<grid, 256>>>(gt, qpos, gwh+OFF_CA_OFF, gwl+OFF_CA_OFF,
                                       gboa, nomask, gbig, TOK, 384, DM, 384, 0);
    }
    // join: value GEMM must be done before deform
    cudaStreamWaitEvent(0, ev_join, 0);
    deform_kernel<<<TOK, 256>>>(gbig, refp, gval, gq);
    {
        dim3 grid(256 / 128, TOK / 128);
        gemm_bf3_kernel<<<grid, 256>>>(gq, (const float*)0, gwh+OFF_CA_OUT, gwl+OFF_CA_OUT,
                                       ca_out_b, nomask, gx, TOK, 256, DM, 256, 0);
    }
    add_ln_kernel<<<TOK, 256>>>(gt, gx, norm1_w, norm1_b, gt);

    // ---- stage 3: FFN ------------------------------------------------------
    {
        dim3 grid(DFFN / 128, TOK / 128);
        gemm_bf3_kernel<<<grid, 256>>>(gt, (const float*)0, gwh+OFF_LIN1, gwl+OFF_LIN1,
                                       lin1_b, nomask, gbig, TOK, DFFN, DM, DFFN, 1);
    }
    {
        dim3 grid(256 / 128, TOK / 128);
        gemm_bf3_kernel<<<grid, 256>>>(gbig, (const float*)0, gwh+OFF_LIN2, gwl+OFF_LIN2,
                                       lin2_b, nomask, gx, TOK, 256, DFFN, 256, 0);
    }
    add_ln_kernel<<<TOK, 256>>>(gt, gx, norm3_w, norm3_b, out);
}